// round 1
// baseline (speedup 1.0000x reference)
#include <cuda_runtime.h>
#include <math.h>

// ---------------------------------------------------------------------------
// DCWTv2InferenceCache: segment-tree cover-set attention decode step.
//
// Inputs (metadata order):
//   d_in[0] v_tokens     float32 [pos, 16, 64]   (pos = in_sizes[0]/1024)
//   d_in[1] q_new        float32 [1, 16, 64]
//   d_in[2] depth_proj_w float32 [18, 64, 64]
//   d_in[3] depth_temp   float32 [18]
//   d_in[4] n_tokens     (unused; pos derived from in_sizes[0])
// Output: float32 [1, 16, 64]
//
// Pipeline:
//   K1 partial_sum : stream all big-node (L>64) chunk rows, per-(seg,k) float4
//                    partial sums  -> g_psum                (HBM bound, ~205MB)
//   K2 reduce      : sum partials, scale by 1/C -> g_f
//   K3 attn        : per (source, head) block: q projection, scores, softmax,
//                    weighted sum. sources = cover nodes + local window.
//   K4 combine     : out = local + mean(node outs)
// ---------------------------------------------------------------------------

#define TOKDIM   1024            // 16 heads * 64 dims
#define HEADS    16
#define HDIM     64
#define SEG      32              // chunks per partial-sum block
#define MAXBIG   16
#define MAXSEGS  96
#define MAXNODES 40

__device__ float g_psum[(size_t)MAXSEGS * 64 * TOKDIM];   // ~25 MB
__device__ float g_f[(size_t)MAXBIG * 64 * TOKDIM];       // ~4 MB
__device__ float g_node_out[MAXNODES * TOKDIM];
__device__ float g_local_out[TOKDIM];

struct BigParams {
    int nBig;
    int a[MAXBIG];            // token offset of node
    int C[MAXBIG];            // number of 64-token chunks
    int segBase[MAXBIG + 1];  // prefix of ceil(C/SEG)
};

struct AttnParams {
    int n;                    // number of cover nodes
    int depth[MAXNODES];
    int K[MAXNODES];          // min(L, 64)
    int isBig[MAXNODES];      // 1 -> read g_f slot off[], 0 -> read v_tokens at token off[]
    int off[MAXNODES];
};

// ---- K1: partial chunk sums ------------------------------------------------
// grid = (totalSegs, 64=k), block = 256. Each block sums up to SEG chunk rows
// (4KB each, fully coalesced float4) for one (node, seg, k).
__global__ void __launch_bounds__(256) partial_sum_kernel(
    const float* __restrict__ V, BigParams P)
{
    int gs  = blockIdx.x;
    int k   = blockIdx.y;
    int tid = threadIdx.x;

    int n = 0;
    while (gs >= P.segBase[n + 1]) n++;
    int seg = gs - P.segBase[n];
    int c0  = seg * SEG;
    int c1  = c0 + SEG;
    if (c1 > P.C[n]) c1 = P.C[n];

    long row0 = (long)P.a[n] + (long)c0 * 64 + k;
    const float4* p = (const float4*)(V + row0 * TOKDIM) + tid;
    const long STR = 64L * TOKDIM / 4;   // float4 stride between chunks (64 tokens)

    float4 a0 = {0,0,0,0}, a1 = {0,0,0,0}, a2 = {0,0,0,0}, a3 = {0,0,0,0};
    int c = c0;
    for (; c + 4 <= c1; c += 4) {
        float4 x0 = p[0];
        float4 x1 = p[STR];
        float4 x2 = p[2 * STR];
        float4 x3 = p[3 * STR];
        a0.x += x0.x; a0.y += x0.y; a0.z += x0.z; a0.w += x0.w;
        a1.x += x1.x; a1.y += x1.y; a1.z += x1.z; a1.w += x1.w;
        a2.x += x2.x; a2.y += x2.y; a2.z += x2.z; a2.w += x2.w;
        a3.x += x3.x; a3.y += x3.y; a3.z += x3.z; a3.w += x3.w;
        p += 4 * STR;
    }
    for (; c < c1; c++) {
        float4 x0 = p[0];
        a0.x += x0.x; a0.y += x0.y; a0.z += x0.z; a0.w += x0.w;
        p += STR;
    }
    float4 acc;
    acc.x = (a0.x + a1.x) + (a2.x + a3.x);
    acc.y = (a0.y + a1.y) + (a2.y + a3.y);
    acc.z = (a0.z + a1.z) + (a2.z + a3.z);
    acc.w = (a0.w + a1.w) + (a2.w + a3.w);

    float4* o = (float4*)(g_psum + ((long)gs * 64 + k) * TOKDIM) + tid;
    *o = acc;
}

// ---- K2: reduce partials -> f ---------------------------------------------
// grid = (nBig, 64=k), block = 256.
__global__ void __launch_bounds__(256) reduce_kernel(BigParams P)
{
    int n   = blockIdx.x;
    int k   = blockIdx.y;
    int tid = threadIdx.x;
    int s0  = P.segBase[n];
    int s1  = P.segBase[n + 1];
    float inv = 1.0f / (float)P.C[n];

    float4 acc = {0,0,0,0};
    for (int s = s0; s < s1; s++) {
        const float4* p = (const float4*)(g_psum + ((long)s * 64 + k) * TOKDIM) + tid;
        float4 x = *p;
        acc.x += x.x; acc.y += x.y; acc.z += x.z; acc.w += x.w;
    }
    acc.x *= inv; acc.y *= inv; acc.z *= inv; acc.w *= inv;
    float4* o = (float4*)(g_f + ((long)n * 64 + k) * TOKDIM) + tid;
    *o = acc;
}

// ---- K3: attention (nodes + local window) ----------------------------------
// grid = (n_nodes + 1, 16 heads), block = 512.
__global__ void __launch_bounds__(512) attn_kernel(
    const float* __restrict__ V,
    const float* __restrict__ q,
    const float* __restrict__ W,
    const float* __restrict__ temp,
    AttnParams P, int pos)
{
    int src = blockIdx.x;
    int h   = blockIdx.y;
    int tid = threadIdx.x;

    __shared__ float q_sh[HDIM];
    __shared__ float qd[HDIM];
    __shared__ float s_sh[512];
    __shared__ float f_sh[64 * HDIM];
    __shared__ float red[512];
    __shared__ float s_scale, s_sum;

    if (tid < HDIM) q_sh[tid] = q[h * HDIM + tid];
    __syncthreads();

    if (src < P.n) {
        // ---- cover-set node attention ----
        int depth = P.depth[src];
        int K     = P.K[src];

        if (tid < HDIM) {
            const float* Wd = W + (long)depth * HDIM * HDIM + (long)tid * HDIM;
            float acc = q_sh[tid];
            #pragma unroll 8
            for (int e = 0; e < HDIM; e++) acc += q_sh[e] * Wd[e];
            qd[tid] = acc;
        }
        if (tid == 0) {
            float t  = temp[depth];
            float sp = log1pf(expf(t));      // softplus
            s_scale  = 1.0f / ((sp + 1e-6f) * 8.0f);  // sqrt(64)=8
        }
        // load f tile [K, 64] for this head into smem
        const float* fsrc = P.isBig[src]
            ? (g_f + (long)P.off[src] * 64 * TOKDIM)
            : (V + (long)P.off[src] * TOKDIM);
        for (int i = tid; i < K * HDIM; i += 512) {
            int k = i >> 6, d = i & 63;
            f_sh[i] = fsrc[(long)k * TOKDIM + h * HDIM + d];
        }
        __syncthreads();

        if (tid < K) {
            float acc = 0.f;
            #pragma unroll 8
            for (int d = 0; d < HDIM; d++) acc += qd[d] * f_sh[tid * HDIM + d];
            s_sh[tid] = acc * s_scale;
        }
        __syncthreads();

        if (tid == 0) {
            float mx = -1e30f;
            for (int k = 0; k < K; k++) mx = fmaxf(mx, s_sh[k]);
            float sum = 0.f;
            for (int k = 0; k < K; k++) {
                float e = expf(s_sh[k] - mx);
                s_sh[k] = e;
                sum += e;
            }
            s_sum = sum;
        }
        __syncthreads();

        if (tid < HDIM) {
            float acc = 0.f;
            for (int k = 0; k < K; k++) acc += s_sh[k] * f_sh[k * HDIM + tid];
            g_node_out[src * TOKDIM + h * HDIM + tid] = acc / s_sum;
        }
    } else {
        // ---- local-window attention over last min(pos,512) tokens ----
        int nloc = pos < 512 ? pos : 512;
        int base = pos - nloc;

        if (tid < nloc) {
            const float* vp = V + (long)(base + tid) * TOKDIM + h * HDIM;
            float acc = 0.f;
            #pragma unroll 8
            for (int d = 0; d < HDIM; d++) acc += q_sh[d] * vp[d];
            s_sh[tid] = acc * 0.125f;        // 1/sqrt(64)
        }
        __syncthreads();

        // block max
        red[tid] = (tid < nloc) ? s_sh[tid] : -1e30f;
        __syncthreads();
        for (int st = 256; st > 0; st >>= 1) {
            if (tid < st) red[tid] = fmaxf(red[tid], red[tid + st]);
            __syncthreads();
        }
        float mx = red[0];
        __syncthreads();

        float e = (tid < nloc) ? expf(s_sh[tid] - mx) : 0.f;
        s_sh[tid] = e;
        red[tid]  = e;
        __syncthreads();
        for (int st = 256; st > 0; st >>= 1) {
            if (tid < st) red[tid] += red[tid + st];
            __syncthreads();
        }
        float wsum = red[0];
        __syncthreads();

        // weighted sum: 8 k-groups x 64 dims
        int g = tid >> 6, d = tid & 63;
        float acc = 0.f;
        for (int k = g; k < nloc; k += 8)
            acc += s_sh[k] * V[(long)(base + k) * TOKDIM + h * HDIM + d];
        red[tid] = acc;
        __syncthreads();
        if (tid < HDIM) {
            float o = 0.f;
            #pragma unroll
            for (int gg = 0; gg < 8; gg++) o += red[gg * 64 + tid];
            g_local_out[h * HDIM + tid] = (wsum > 0.f) ? (o / wsum) : 0.f;
        }
    }
}

// ---- K4: combine -------------------------------------------------------------
__global__ void combine_kernel(float* __restrict__ out, int n_nodes, int out_size)
{
    int j = threadIdx.x;
    if (j < out_size && j < TOKDIM) {
        float t = 0.f;
        for (int n = 0; n < n_nodes; n++) t += g_node_out[n * TOKDIM + j];
        float tree = (n_nodes > 0) ? (t / (float)n_nodes) : 0.f;
        out[j] = g_local_out[j] + tree;
    }
}

// ---------------------------------------------------------------------------
extern "C" void kernel_launch(void* const* d_in, const int* in_sizes, int n_in,
                              void* d_out, int out_size)
{
    const float* V    = (const float*)d_in[0];
    const float* q    = (const float*)d_in[1];
    const float* W    = (const float*)d_in[2];
    const float* temp = (const float*)d_in[3];

    const int pos = in_sizes[0] / TOKDIM;

    const int LOG_N = 17;
    const long LEAF_START = 1L << LOG_N;
    const long MAX_LEN = 65536;

    BigParams bp;  bp.nBig = 0;
    AttnParams ap; ap.n = 0;

    auto addNode = [&](long idx) {
        int fl = 0; long t = idx;
        while (t > 1) { t >>= 1; fl++; }
        int depth = LOG_N - fl;
        long L = 1L << depth;
        long a = (idx << depth) - LEAF_START;
        int ni = ap.n++;
        ap.depth[ni] = depth;
        ap.K[ni] = (int)(L < 64 ? L : 64);
        if (L > 64) {
            int bi = bp.nBig++;
            bp.a[bi] = (int)a;
            bp.C[bi] = (int)(L / 64);
            ap.isBig[ni] = 1;
            ap.off[ni] = bi;
        } else {
            ap.isBig[ni] = 0;
            ap.off[ni] = (int)a;
        }
    };

    long l = LEAF_START;
    long r = LEAF_START + (pos < MAX_LEN ? (long)pos : MAX_LEN);
    while (l < r) {
        if (l & 1) { addNode(l); l++; }
        if (r & 1) { r--; addNode(r); }
        l >>= 1; r >>= 1;
    }

    bp.segBase[0] = 0;
    for (int i = 0; i < bp.nBig; i++)
        bp.segBase[i + 1] = bp.segBase[i] + (bp.C[i] + SEG - 1) / SEG;
    int totalSegs = bp.nBig ? bp.segBase[bp.nBig] : 0;

    if (totalSegs > 0) {
        partial_sum_kernel<<<dim3(totalSegs, 64), 256>>>(V, bp);
        reduce_kernel<<<dim3(bp.nBig, 64), 256>>>(bp);
    }
    attn_kernel<<<dim3(ap.n + 1, HEADS), 512>>>(V, q, W, temp, ap, pos);
    combine_kernel<<<1, 1024>>>((float*)d_out, ap.n, out_size);
}

// round 2
// speedup vs baseline: 1.0203x; 1.0203x over previous
#include <cuda_runtime.h>
#include <math.h>

// ---------------------------------------------------------------------------
// DCWTv2InferenceCache: segment-tree cover-set attention decode step.
//
//   d_in[0] v_tokens     float32 [pos, 16, 64]   (pos = in_sizes[0]/1024)
//   d_in[1] q_new        float32 [1, 16, 64]
//   d_in[2] depth_proj_w float32 [18, 64, 64]
//   d_in[3] depth_temp   float32 [18]
//   out: float32 [1, 16, 64]
//
// Pipeline (3 graph nodes of real work):
//   memset g_f, memset d_out
//   K1 partial : perfectly-balanced stream of all big-node (L>64) chunk rows;
//                each block covers an equal slice of (chunk,k) units and
//                red-adds its 1/C-scaled partial rows into g_f (L2-resident).
//   K2 attn    : per (source, head) block: q proj, scores, softmax, weighted
//                sum; red-adds (local + mean-of-nodes) directly into d_out.
// ---------------------------------------------------------------------------

#define TOKDIM   1024            // 16 heads * 64 dims
#define HEADS    16
#define HDIM     64
#define MAXBIG   16
#define MAXNODES 40
#define GRID_P   1216            // 152 SMs * 8 blocks (256 thr) = full residency

__device__ float g_f[(size_t)MAXBIG * 64 * TOKDIM];   // 4 MB (only nBig*256KB used)

struct PartParams {
    int  nBig;
    int  a[MAXBIG];              // token offset of node
    int  C[MAXBIG];              // chunks (of 64 tokens) in node
    float inv[MAXBIG];           // 1/C
    long unitBase[MAXBIG + 1];   // prefix of C[n]*64 units
};

struct AttnParams {
    int n;                       // number of cover nodes
    float inv_n;                 // 1/n
    int depth[MAXNODES];
    int K[MAXNODES];             // min(L, 64)
    int isBig[MAXNODES];         // 1 -> g_f slot off[], 0 -> v_tokens token off[]
    int off[MAXNODES];
};

// ---- K1: balanced partial chunk sums -> red into g_f ------------------------
// One unit = one (chunk, k) row of 1024 floats (4KB, fully coalesced).
// Block b owns units [b*U/G, (b+1)*U/G): contiguous chunks within a (node,k)
// row, so a block has ~1-2 "runs", each ending in one 4KB red-add to g_f.
__global__ void __launch_bounds__(256) partial_kernel(
    const float* __restrict__ V, PartParams P, long U)
{
    const int  tid = threadIdx.x;
    long u  = (long)blockIdx.x       * U / GRID_P;
    long u1 = ((long)blockIdx.x + 1) * U / GRID_P;

    while (u < u1) {
        int n = 0;
        while (u >= P.unitBase[n + 1]) n++;
        long rem = u - P.unitBase[n];
        int  k   = (int)(rem / P.C[n]);
        int  c   = (int)(rem % P.C[n]);
        long run = P.C[n] - c;
        if (run > u1 - u) run = u1 - u;

        const float4* p = (const float4*)(V + ((long)P.a[n] + (long)c * 64 + k) * TOKDIM) + tid;
        const long STR = 64L * TOKDIM / 4;    // float4 stride between chunks

        float4 a0 = {0,0,0,0}, a1 = {0,0,0,0}, a2 = {0,0,0,0}, a3 = {0,0,0,0};
        long r = 0;
        for (; r + 4 <= run; r += 4) {
            float4 x0 = p[0];
            float4 x1 = p[STR];
            float4 x2 = p[2 * STR];
            float4 x3 = p[3 * STR];
            a0.x += x0.x; a0.y += x0.y; a0.z += x0.z; a0.w += x0.w;
            a1.x += x1.x; a1.y += x1.y; a1.z += x1.z; a1.w += x1.w;
            a2.x += x2.x; a2.y += x2.y; a2.z += x2.z; a2.w += x2.w;
            a3.x += x3.x; a3.y += x3.y; a3.z += x3.z; a3.w += x3.w;
            p += 4 * STR;
        }
        for (; r < run; r++) {
            float4 x0 = p[0];
            a0.x += x0.x; a0.y += x0.y; a0.z += x0.z; a0.w += x0.w;
            p += STR;
        }
        float s = P.inv[n];
        float4 acc;
        acc.x = ((a0.x + a1.x) + (a2.x + a3.x)) * s;
        acc.y = ((a0.y + a1.y) + (a2.y + a3.y)) * s;
        acc.z = ((a0.z + a1.z) + (a2.z + a3.z)) * s;
        acc.w = ((a0.w + a1.w) + (a2.w + a3.w)) * s;

        float* o = g_f + ((long)n * 64 + k) * TOKDIM + tid * 4;
        atomicAdd(o + 0, acc.x);
        atomicAdd(o + 1, acc.y);
        atomicAdd(o + 2, acc.z);
        atomicAdd(o + 3, acc.w);

        u += run;
    }
}

// ---- K2: attention (nodes + local window), red into out ---------------------
// grid = (n_nodes + 1, 16 heads), block = 512.
__global__ void __launch_bounds__(512) attn_kernel(
    const float* __restrict__ V,
    const float* __restrict__ q,
    const float* __restrict__ W,
    const float* __restrict__ temp,
    AttnParams P, int pos, float* __restrict__ out)
{
    int src = blockIdx.x;
    int h   = blockIdx.y;
    int tid = threadIdx.x;

    __shared__ float q_sh[HDIM];
    __shared__ float qd[HDIM];
    __shared__ float s_sh[512];
    __shared__ float f_sh[64 * HDIM];
    __shared__ float red[512];
    __shared__ float s_scale, s_sum;

    if (tid < HDIM) q_sh[tid] = q[h * HDIM + tid];
    __syncthreads();

    if (src < P.n) {
        // ---- cover-set node attention ----
        int depth = P.depth[src];
        int K     = P.K[src];

        if (tid < HDIM) {
            const float* Wd = W + (long)depth * HDIM * HDIM + (long)tid * HDIM;
            float acc = q_sh[tid];
            #pragma unroll 8
            for (int e = 0; e < HDIM; e++) acc += q_sh[e] * Wd[e];
            qd[tid] = acc;
        }
        if (tid == 0) {
            float t  = temp[depth];
            float sp = log1pf(expf(t));               // softplus
            s_scale  = 1.0f / ((sp + 1e-6f) * 8.0f);  // sqrt(64)=8
        }
        const float* fsrc = P.isBig[src]
            ? (g_f + (long)P.off[src] * 64 * TOKDIM)
            : (V + (long)P.off[src] * TOKDIM);
        for (int i = tid; i < K * HDIM; i += 512) {
            int k = i >> 6, d = i & 63;
            f_sh[i] = fsrc[(long)k * TOKDIM + h * HDIM + d];
        }
        __syncthreads();

        if (tid < K) {
            float acc = 0.f;
            #pragma unroll 8
            for (int d = 0; d < HDIM; d++) acc += qd[d] * f_sh[tid * HDIM + d];
            s_sh[tid] = acc * s_scale;
        }
        __syncthreads();

        if (tid == 0) {
            float mx = -1e30f;
            for (int k = 0; k < K; k++) mx = fmaxf(mx, s_sh[k]);
            float sum = 0.f;
            for (int k = 0; k < K; k++) {
                float e = expf(s_sh[k] - mx);
                s_sh[k] = e;
                sum += e;
            }
            s_sum = sum;
        }
        __syncthreads();

        if (tid < HDIM) {
            float acc = 0.f;
            for (int k = 0; k < K; k++) acc += s_sh[k] * f_sh[k * HDIM + tid];
            atomicAdd(out + h * HDIM + tid, (acc / s_sum) * P.inv_n);
        }
    } else {
        // ---- local-window attention over last min(pos,512) tokens ----
        int nloc = pos < 512 ? pos : 512;
        int base = pos - nloc;

        if (tid < nloc) {
            const float* vp = V + (long)(base + tid) * TOKDIM + h * HDIM;
            float acc = 0.f;
            #pragma unroll 8
            for (int d = 0; d < HDIM; d++) acc += q_sh[d] * vp[d];
            s_sh[tid] = acc * 0.125f;                 // 1/sqrt(64)
        }
        __syncthreads();

        red[tid] = (tid < nloc) ? s_sh[tid] : -1e30f;
        __syncthreads();
        for (int st = 256; st > 0; st >>= 1) {
            if (tid < st) red[tid] = fmaxf(red[tid], red[tid + st]);
            __syncthreads();
        }
        float mx = red[0];
        __syncthreads();

        float e = (tid < nloc) ? expf(s_sh[tid] - mx) : 0.f;
        s_sh[tid] = e;
        red[tid]  = e;
        __syncthreads();
        for (int st = 256; st > 0; st >>= 1) {
            if (tid < st) red[tid] += red[tid + st];
            __syncthreads();
        }
        float wsum = red[0];
        __syncthreads();

        int g = tid >> 6, d = tid & 63;
        float acc = 0.f;
        for (int k = g; k < nloc; k += 8)
            acc += s_sh[k] * V[(long)(base + k) * TOKDIM + h * HDIM + d];
        red[tid] = acc;
        __syncthreads();
        if (tid < HDIM) {
            float o = 0.f;
            #pragma unroll
            for (int gg = 0; gg < 8; gg++) o += red[gg * 64 + tid];
            atomicAdd(out + h * HDIM + tid, (wsum > 0.f) ? (o / wsum) : 0.f);
        }
    }
}

// ---------------------------------------------------------------------------
extern "C" void kernel_launch(void* const* d_in, const int* in_sizes, int n_in,
                              void* d_out, int out_size)
{
    const float* V    = (const float*)d_in[0];
    const float* q    = (const float*)d_in[1];
    const float* W    = (const float*)d_in[2];
    const float* temp = (const float*)d_in[3];

    const int pos = in_sizes[0] / TOKDIM;

    const int  LOG_N      = 17;
    const long LEAF_START = 1L << LOG_N;
    const long MAX_LEN    = 65536;

    PartParams bp;  bp.nBig = 0;
    AttnParams ap;  ap.n = 0;

    auto addNode = [&](long idx) {
        int fl = 0; long t = idx;
        while (t > 1) { t >>= 1; fl++; }
        int depth = LOG_N - fl;
        long L = 1L << depth;
        long a = (idx << depth) - LEAF_START;
        int ni = ap.n++;
        ap.depth[ni] = depth;
        ap.K[ni] = (int)(L < 64 ? L : 64);
        if (L > 64) {
            int bi = bp.nBig++;
            bp.a[bi]   = (int)a;
            bp.C[bi]   = (int)(L / 64);
            bp.inv[bi] = 1.0f / (float)(L / 64);
            ap.isBig[ni] = 1;
            ap.off[ni]   = bi;
        } else {
            ap.isBig[ni] = 0;
            ap.off[ni]   = (int)a;
        }
    };

    long l = LEAF_START;
    long r = LEAF_START + (pos < MAX_LEN ? (long)pos : MAX_LEN);
    while (l < r) {
        if (l & 1) { addNode(l); l++; }
        if (r & 1) { r--; addNode(r); }
        l >>= 1; r >>= 1;
    }
    ap.inv_n = ap.n > 0 ? 1.0f / (float)ap.n : 0.f;

    bp.unitBase[0] = 0;
    for (int i = 0; i < bp.nBig; i++)
        bp.unitBase[i + 1] = bp.unitBase[i] + (long)bp.C[i] * 64;
    long U = bp.nBig ? bp.unitBase[bp.nBig] : 0;

    // zero the output (poisoned by harness) and the g_f accumulator
    cudaMemsetAsync(d_out, 0, (size_t)out_size * sizeof(float));
    if (U > 0) {
        void* gf_ptr = nullptr;
        cudaGetSymbolAddress(&gf_ptr, g_f);
        cudaMemsetAsync(gf_ptr, 0, (size_t)bp.nBig * 64 * TOKDIM * sizeof(float));
        partial_kernel<<<GRID_P, 256>>>(V, bp, U);
    }
    attn_kernel<<<dim3(ap.n + 1, HEADS), 512>>>(V, q, W, temp, ap, pos, (float*)d_out);
}

// round 3
// speedup vs baseline: 1.2547x; 1.2298x over previous
#include <cuda_runtime.h>
#include <math.h>

// ---------------------------------------------------------------------------
// DCWTv2InferenceCache: segment-tree cover-set attention decode step.
//
//   d_in[0] v_tokens     float32 [pos, 16, 64]   (pos = in_sizes[0]/1024)
//   d_in[1] q_new        float32 [1, 16, 64]
//   d_in[2] depth_proj_w float32 [18, 64, 64]
//   d_in[3] depth_temp   float32 [18]
//   out: float32 [1, 16, 64]
//
// Graph: memset d_out, memset g_f, K1 partial (HBM stream), K2 attn (latency-
// optimized: one batched smem load phase, parallel softmax, parallel wsum).
// ---------------------------------------------------------------------------

#define TOKDIM   1024            // 16 heads * 64 dims
#define HEADS    16
#define HDIM     64
#define MAXBIG   16
#define MAXNODES 40
#define GRID_P   1216            // 152 SMs * 8 blocks (256 thr)

__device__ float g_f[(size_t)MAXBIG * 64 * TOKDIM];   // up to 4 MB

struct PartParams {
    int  nBig;
    int  a[MAXBIG];              // token offset of node
    int  C[MAXBIG];              // chunks (of 64 tokens) in node
    float inv[MAXBIG];           // 1/C
    long unitBase[MAXBIG + 1];   // prefix of C[n]*64 units
};

struct AttnParams {
    int n;                       // number of cover nodes
    float inv_n;                 // 1/n
    int depth[MAXNODES];
    int K[MAXNODES];             // min(L, 64)
    int isBig[MAXNODES];         // 1 -> g_f slot off[], 0 -> v_tokens token off[]
    int off[MAXNODES];
};

// ---- K1: balanced partial chunk sums -> red into g_f ------------------------
__global__ void __launch_bounds__(256) partial_kernel(
    const float* __restrict__ V, PartParams P, long U)
{
    const int tid = threadIdx.x;
    long u  = (long)blockIdx.x       * U / GRID_P;
    long u1 = ((long)blockIdx.x + 1) * U / GRID_P;

    while (u < u1) {
        int n = 0;
        while (u >= P.unitBase[n + 1]) n++;
        long rem = u - P.unitBase[n];
        int  k   = (int)(rem / P.C[n]);
        int  c   = (int)(rem % P.C[n]);
        long run = P.C[n] - c;
        if (run > u1 - u) run = u1 - u;

        const float4* p = (const float4*)(V + ((long)P.a[n] + (long)c * 64 + k) * TOKDIM) + tid;
        const long STR = 64L * TOKDIM / 4;    // float4 stride between chunks

        float4 a0 = {0,0,0,0}, a1 = {0,0,0,0}, a2 = {0,0,0,0}, a3 = {0,0,0,0};
        long r = 0;
        for (; r + 8 <= run; r += 8) {
            float4 x0 = p[0];
            float4 x1 = p[STR];
            float4 x2 = p[2 * STR];
            float4 x3 = p[3 * STR];
            float4 x4 = p[4 * STR];
            float4 x5 = p[5 * STR];
            float4 x6 = p[6 * STR];
            float4 x7 = p[7 * STR];
            a0.x += x0.x; a0.y += x0.y; a0.z += x0.z; a0.w += x0.w;
            a1.x += x1.x; a1.y += x1.y; a1.z += x1.z; a1.w += x1.w;
            a2.x += x2.x; a2.y += x2.y; a2.z += x2.z; a2.w += x2.w;
            a3.x += x3.x; a3.y += x3.y; a3.z += x3.z; a3.w += x3.w;
            a0.x += x4.x; a0.y += x4.y; a0.z += x4.z; a0.w += x4.w;
            a1.x += x5.x; a1.y += x5.y; a1.z += x5.z; a1.w += x5.w;
            a2.x += x6.x; a2.y += x6.y; a2.z += x6.z; a2.w += x6.w;
            a3.x += x7.x; a3.y += x7.y; a3.z += x7.z; a3.w += x7.w;
            p += 8 * STR;
        }
        for (; r < run; r++) {
            float4 x0 = p[0];
            a0.x += x0.x; a0.y += x0.y; a0.z += x0.z; a0.w += x0.w;
            p += STR;
        }
        float s = P.inv[n];
        float4 acc;
        acc.x = ((a0.x + a1.x) + (a2.x + a3.x)) * s;
        acc.y = ((a0.y + a1.y) + (a2.y + a3.y)) * s;
        acc.z = ((a0.z + a1.z) + (a2.z + a3.z)) * s;
        acc.w = ((a0.w + a1.w) + (a2.w + a3.w)) * s;

        float* o = g_f + ((long)n * 64 + k) * TOKDIM + tid * 4;
        atomicAdd(o + 0, acc.x);
        atomicAdd(o + 1, acc.y);
        atomicAdd(o + 2, acc.z);
        atomicAdd(o + 3, acc.w);

        u += run;
    }
}

// ---- K2: attention (nodes + local window), red into out ---------------------
// grid = (n_nodes + 1, 16 heads), block = 512.
__global__ void __launch_bounds__(512) attn_kernel(
    const float* __restrict__ V,
    const float* __restrict__ q,
    const float* __restrict__ W,
    const float* __restrict__ temp,
    AttnParams P, int pos, float* __restrict__ out)
{
    const int src = blockIdx.x;
    const int h   = blockIdx.y;
    const int tid = threadIdx.x;

    __shared__ float W_sh[HDIM * 65];   // W[depth] transposed, padded (node path)
    __shared__ float f_sh[HDIM * 65];   // f tile [K,64], padded
    __shared__ float q_sh[HDIM];
    __shared__ float qd[HDIM];
    __shared__ float s_sh[512];         // scores / exp weights
    __shared__ float red[512];
    __shared__ float s_scale, s_mx, s_sum;

    if (src < P.n) {
        // ================= cover-set node attention =================
        const int depth = P.depth[src];
        const int K     = P.K[src];

        // --- batched, coalesced load phase: q, W[depth], f tile, temp ---
        if (tid < HDIM) q_sh[tid] = q[h * HDIM + tid];

        const float* Wd = W + (long)depth * HDIM * HDIM;
        #pragma unroll
        for (int i = tid; i < HDIM * HDIM; i += 512) {
            int d = i >> 6, e = i & 63;
            W_sh[e * 65 + d] = Wd[i];          // transposed store (conflict-free)
        }
        const float* fsrc = P.isBig[src]
            ? (g_f + (long)P.off[src] * 64 * TOKDIM)
            : (V + (long)P.off[src] * TOKDIM);
        for (int i = tid; i < K * HDIM; i += 512) {
            int k = i >> 6, d = i & 63;
            f_sh[k * 65 + d] = fsrc[(long)k * TOKDIM + h * HDIM + d];
        }
        if (tid == 0) {
            float t  = temp[depth];
            float sp = log1pf(expf(t));               // softplus
            s_scale  = 1.0f / ((sp + 1e-6f) * 8.0f);  // sqrt(64)=8
        }
        __syncthreads();

        // --- qd = q + q @ W^T (64 threads, all smem, conflict-free) ---
        if (tid < HDIM) {
            float acc = q_sh[tid];
            #pragma unroll
            for (int e = 0; e < HDIM; e++) acc += q_sh[e] * W_sh[e * 65 + tid];
            qd[tid] = acc;
        }
        __syncthreads();

        // --- scores (K threads) ---
        float sc = -1e30f;
        if (tid < K) {
            float acc = 0.f;
            #pragma unroll
            for (int d = 0; d < HDIM; d++) acc += qd[d] * f_sh[tid * 65 + d];
            sc = acc * s_scale;
        }
        if (tid < 64) red[tid] = sc;
        __syncthreads();

        // --- max over 64 (warp 0 via shuffle) ---
        if (tid < 32) {
            float m = fmaxf(red[tid], red[tid + 32]);
            #pragma unroll
            for (int o = 16; o > 0; o >>= 1)
                m = fmaxf(m, __shfl_xor_sync(0xffffffff, m, o));
            if (tid == 0) s_mx = m;
        }
        __syncthreads();

        float e = (tid < K) ? expf(sc - s_mx) : 0.f;
        if (tid < 64) { s_sh[tid] = e; red[tid] = e; }
        __syncthreads();

        if (tid < 32) {
            float sm = red[tid] + red[tid + 32];
            #pragma unroll
            for (int o = 16; o > 0; o >>= 1)
                sm += __shfl_xor_sync(0xffffffff, sm, o);
            if (tid == 0) s_sum = sm;
        }
        __syncthreads();

        // --- weighted sum: 8 k-groups x 64 dims, then combine ---
        {
            int g = tid >> 6, d = tid & 63;
            float acc = 0.f;
            for (int k = g; k < K; k += 8) acc += s_sh[k] * f_sh[k * 65 + d];
            red[tid] = acc;
        }
        __syncthreads();
        if (tid < HDIM) {
            float o = 0.f;
            #pragma unroll
            for (int gg = 0; gg < 8; gg++) o += red[gg * 64 + tid];
            atomicAdd(out + h * HDIM + tid, (o / s_sum) * P.inv_n);
        }
    } else {
        // ================= local-window attention =================
        const int nloc = pos < 512 ? pos : 512;
        const int base = pos - nloc;

        if (tid < HDIM) q_sh[tid] = q[h * HDIM + tid];
        __syncthreads();

        float sc = -1e30f;
        if (tid < nloc) {
            const float4* vp = (const float4*)(V + (long)(base + tid) * TOKDIM + h * HDIM);
            const float4* qp = (const float4*)q_sh;
            float acc = 0.f;
            #pragma unroll
            for (int i = 0; i < 16; i++) {
                float4 x = vp[i];
                float4 qq = qp[i];
                acc += x.x * qq.x + x.y * qq.y + x.z * qq.z + x.w * qq.w;
            }
            sc = acc * 0.125f;                 // 1/sqrt(64)
        }
        red[tid] = sc;
        __syncthreads();
        #pragma unroll
        for (int st = 256; st >= 32; st >>= 1) {
            if (tid < st) red[tid] = fmaxf(red[tid], red[tid + st]);
            __syncthreads();
        }
        if (tid < 32) {
            float m = red[tid];
            #pragma unroll
            for (int o = 16; o > 0; o >>= 1)
                m = fmaxf(m, __shfl_xor_sync(0xffffffff, m, o));
            if (tid == 0) s_mx = m;
        }
        __syncthreads();

        float e = (tid < nloc) ? expf(sc - s_mx) : 0.f;
        s_sh[tid] = e;
        red[tid]  = e;
        __syncthreads();
        #pragma unroll
        for (int st = 256; st >= 32; st >>= 1) {
            if (tid < st) red[tid] += red[tid + st];
            __syncthreads();
        }
        if (tid < 32) {
            float sm = red[tid];
            #pragma unroll
            for (int o = 16; o > 0; o >>= 1)
                sm += __shfl_xor_sync(0xffffffff, sm, o);
            if (tid == 0) s_sum = sm;
        }
        __syncthreads();

        {
            int g = tid >> 6, d = tid & 63;
            float acc = 0.f;
            for (int k = g; k < nloc; k += 8)
                acc += s_sh[k] * V[(long)(base + k) * TOKDIM + h * HDIM + d];
            red[tid] = acc;
        }
        __syncthreads();
        if (tid < HDIM) {
            float o = 0.f;
            #pragma unroll
            for (int gg = 0; gg < 8; gg++) o += red[gg * 64 + tid];
            atomicAdd(out + h * HDIM + tid, (s_sum > 0.f) ? (o / s_sum) : 0.f);
        }
    }
}

// ---------------------------------------------------------------------------
extern "C" void kernel_launch(void* const* d_in, const int* in_sizes, int n_in,
                              void* d_out, int out_size)
{
    const float* V    = (const float*)d_in[0];
    const float* q    = (const float*)d_in[1];
    const float* W    = (const float*)d_in[2];
    const float* temp = (const float*)d_in[3];

    const int pos = in_sizes[0] / TOKDIM;

    const int  LOG_N      = 17;
    const long LEAF_START = 1L << LOG_N;
    const long MAX_LEN    = 65536;

    PartParams bp;  bp.nBig = 0;
    AttnParams ap;  ap.n = 0;

    auto addNode = [&](long idx) {
        int fl = 0; long t = idx;
        while (t > 1) { t >>= 1; fl++; }
        int depth = LOG_N - fl;
        long L = 1L << depth;
        long a = (idx << depth) - LEAF_START;
        int ni = ap.n++;
        ap.depth[ni] = depth;
        ap.K[ni] = (int)(L < 64 ? L : 64);
        if (L > 64) {
            int bi = bp.nBig++;
            bp.a[bi]   = (int)a;
            bp.C[bi]   = (int)(L / 64);
            bp.inv[bi] = 1.0f / (float)(L / 64);
            ap.isBig[ni] = 1;
            ap.off[ni]   = bi;
        } else {
            ap.isBig[ni] = 0;
            ap.off[ni]   = (int)a;
        }
    };

    long l = LEAF_START;
    long r = LEAF_START + (pos < MAX_LEN ? (long)pos : MAX_LEN);
    while (l < r) {
        if (l & 1) { addNode(l); l++; }
        if (r & 1) { r--; addNode(r); }
        l >>= 1; r >>= 1;
    }
    ap.inv_n = ap.n > 0 ? 1.0f / (float)ap.n : 0.f;

    bp.unitBase[0] = 0;
    for (int i = 0; i < bp.nBig; i++)
        bp.unitBase[i + 1] = bp.unitBase[i] + (long)bp.C[i] * 64;
    long U = bp.nBig ? bp.unitBase[bp.nBig] : 0;

    cudaMemsetAsync(d_out, 0, (size_t)out_size * sizeof(float));
    if (U > 0) {
        void* gf_ptr = nullptr;
        cudaGetSymbolAddress(&gf_ptr, g_f);
        cudaMemsetAsync(gf_ptr, 0, (size_t)bp.nBig * 64 * TOKDIM * sizeof(float));
        partial_kernel<<<GRID_P, 256>>>(V, bp, U);
    }
    attn_kernel<<<dim3(ap.n + 1, HEADS), 512>>>(V, q, W, temp, ap, pos, (float*)d_out);
}